// round 14
// baseline (speedup 1.0000x reference)
#include <cuda_runtime.h>
#include <cstdint>

#define NN 50000
#define HH 128
#define GG 512
#define CC 10
#define CAP 64        // padded CSR row capacity (Poisson(16): P(deg>=64) ~ 1e-20)
#define TS 132        // padded SMEM row stride (floats)

// ---------------- scratch (no allocs allowed) ----------------
__device__ __align__(16) uint32_t g_Hbf[NN * 64];    // gemm out, bf16x2 (gather target)
__device__ __align__(16) float g_B[NN * HH];         // fp32 intermediate
__device__ float g_invcnt[GG];
__device__ int   g_deg[NN];                          // zero at load; re-zeroed at graph end
__device__ __align__(16) int g_csr[NN * CAP];        // padded CSR rows
__device__ int g_ei64;
__device__ int g_b64;

__device__ __forceinline__ float blo(uint32_t v) { return __uint_as_float(v << 16); }
__device__ __forceinline__ float bhi(uint32_t v) { return __uint_as_float(v & 0xffff0000u); }
__device__ __forceinline__ uint32_t pack_bf16(float lo, float hi) {
    uint32_t r;
    asm("cvt.rn.bf16x2.f32 %0, %1, %2;" : "=r"(r) : "f"(hi), "f"(lo));
    return r;
}

// ---------------- dtype detect only (tiny, critical-path head) ----------------
__global__ void detect_kernel(const unsigned* __restrict__ ei,
                              const unsigned* __restrict__ bat) {
    unsigned oe = 0, ob = 0;
    int lane = threadIdx.x;
    for (int j = lane; j < 1024; j += 32) {
        oe |= ei[2 * j + 1];
        ob |= bat[2 * j + 1];
    }
#pragma unroll
    for (int off = 16; off; off >>= 1) {
        oe |= __shfl_xor_sync(0xffffffffu, oe, off);
        ob |= __shfl_xor_sync(0xffffffffu, ob, off);
    }
    if (lane == 0) { g_ei64 = (oe == 0u); g_b64 = (ob == 0u); }
}

// graph-end cleanup: restore deg=0 for the next replay
__global__ void cleanup_deg_kernel() {
    int i = blockIdx.x * blockDim.x + threadIdx.x;
    if (i < NN) g_deg[i] = 0;
}

// ---------------- side-stream prep: inv counts via binary search + out=bl ------
__global__ void prep_kernel(const void* __restrict__ bat,
                            const float* __restrict__ bl,
                            float* __restrict__ out) {
    __shared__ int sb64;
    int t = threadIdx.x;                       // 512 threads
    if (t < 32) {
        unsigned ob = 0;
        for (int j = t; j < 1024; j += 32) ob |= ((const unsigned*)bat)[2 * j + 1];
#pragma unroll
        for (int off = 16; off; off >>= 1) ob |= __shfl_xor_sync(0xffffffffu, ob, off);
        if (t == 0) sb64 = (ob == 0u);
    }
    __syncthreads();
    int b64 = sb64;
    // lower_bound(g) and lower_bound(g+1) over sorted bat[0..NN)
    int lo = 0, hi = NN;
    while (lo < hi) {
        int mid = (lo + hi) >> 1;
        long long v = b64 ? ((const long long*)bat)[mid] : (long long)((const int*)bat)[mid];
        if (v < (long long)t) lo = mid + 1; else hi = mid;
    }
    int l1 = lo;
    lo = 0; hi = NN;
    while (lo < hi) {
        int mid = (lo + hi) >> 1;
        long long v = b64 ? ((const long long*)bat)[mid] : (long long)((const int*)bat)[mid];
        if (v < (long long)(t + 1)) lo = mid + 1; else hi = mid;
    }
    int cnt = lo - l1;
    g_invcnt[t] = 1.0f / fmaxf((float)cnt, 1.0f);
#pragma unroll
    for (int j = 0; j < CC; j++) out[t * CC + j] = __ldg(bl + j);
}

// ---------------- single-pass padded-CSR fill (deg counted in place) ----------
__global__ void fill_direct_kernel(const void* __restrict__ ei, int E) {
    int e = blockIdx.x * blockDim.x + threadIdx.x;
    if (e >= E) return;
    int src, dst;
    if (g_ei64) {
        src = (int)((const long long*)ei)[e];
        dst = (int)((const long long*)ei)[E + e];
    } else {
        src = ((const int*)ei)[e];
        dst = ((const int*)ei)[E + e];
    }
    int slot = atomicAdd(&g_deg[dst], 1);
    g_csr[dst * CAP + slot] = src;
}

// ---------------------------------------------------------------------------
// Split-neighbor agg core: 2 warps per node; warp p takes edges e ≡ p (mod 2),
// 2 gathers in flight. Returns this warp's partial (float4 per lane).
// p==0 partial includes the self-loop term.
// ---------------------------------------------------------------------------
__device__ __forceinline__ float4 agg_partial(const uint32_t* __restrict__ hb,
                                              int w, int p, int lane, float dd,
                                              int degw) {
    float ax = 0.f, ay = 0.f, az = 0.f, aw = 0.f;
    float bx = 0.f, by = 0.f, bz = 0.f, bw = 0.f;
    if (p == 0) {
        float sc = dd * dd;
        uint2 sv = __ldg((const uint2*)hb + w * 32 + lane);
        ax = blo(sv.x) * sc; ay = bhi(sv.x) * sc;
        az = blo(sv.y) * sc; aw = bhi(sv.y) * sc;
    }
    const int* row = g_csr + w * CAP;
    int e = p;
    for (; e + 2 < degw; e += 4) {
        int sa = row[e], sb = row[e + 2];
        uint2 pa = __ldg((const uint2*)hb + sa * 32 + lane);
        uint2 pb = __ldg((const uint2*)hb + sb * 32 + lane);
        float na = rsqrtf((float)g_deg[sa] + 1.0f) * dd;
        float nb = rsqrtf((float)g_deg[sb] + 1.0f) * dd;
        ax = fmaf(blo(pa.x), na, ax);
        ay = fmaf(bhi(pa.x), na, ay);
        az = fmaf(blo(pa.y), na, az);
        aw = fmaf(bhi(pa.y), na, aw);
        bx = fmaf(blo(pb.x), nb, bx);
        by = fmaf(bhi(pb.x), nb, by);
        bz = fmaf(blo(pb.y), nb, bz);
        bw = fmaf(bhi(pb.y), nb, bw);
    }
    if (e < degw) {
        int sa = row[e];
        uint2 pa = __ldg((const uint2*)hb + sa * 32 + lane);
        float na = rsqrtf((float)g_deg[sa] + 1.0f) * dd;
        ax = fmaf(blo(pa.x), na, ax);
        ay = fmaf(bhi(pa.x), na, ay);
        az = fmaf(blo(pa.y), na, az);
        aw = fmaf(bhi(pa.y), na, aw);
    }
    return make_float4(ax + bx, ay + by, az + bz, aw + bw);
}

// layer-1 agg: 4 nodes/block, 2 warps/node; fp32 out
__global__ void __launch_bounds__(256)
agg_kernel(const uint32_t* __restrict__ hb, const float* __restrict__ bias,
           float* __restrict__ out) {
    __shared__ float sh[4][128];
    int wid = threadIdx.x >> 5, lane = threadIdx.x & 31;
    int nl = wid >> 1, p = wid & 1;
    int w = blockIdx.x * 4 + nl;                 // grid 12500*4 == NN exactly
    int degw = g_deg[w];
    float dd = rsqrtf((float)degw + 1.0f);
    float4 part = agg_partial(hb, w, p, lane, dd, degw);
    if (p == 1) *(float4*)&sh[nl][lane * 4] = part;
    __syncthreads();
    if (p == 0) {
        float4 o = *(float4*)&sh[nl][lane * 4];
        int c = lane * 4;
        float4 acc;
        acc.x = fmaxf(part.x + o.x + __ldg(bias + c + 0), 0.f);
        acc.y = fmaxf(part.y + o.y + __ldg(bias + c + 1), 0.f);
        acc.z = fmaxf(part.z + o.z + __ldg(bias + c + 2), 0.f);
        acc.w = fmaxf(part.w + o.w + __ldg(bias + c + 3), 0.f);
        ((float4*)out)[w * 32 + lane] = acc;
    }
}

// layer-2 agg fused with mean-pool + classifier head: REDs 10 floats per node
__global__ void __launch_bounds__(256)
agg_pool_head_kernel(const uint32_t* __restrict__ hb,
                     const float* __restrict__ bias,
                     const void* __restrict__ bat,
                     const float* __restrict__ Wl,
                     float* __restrict__ out) {
    __shared__ float sh[4][128];
    int wid = threadIdx.x >> 5, lane = threadIdx.x & 31;
    int nl = wid >> 1, p = wid & 1;
    int w = blockIdx.x * 4 + nl;
    int degw = g_deg[w];
    float dd = rsqrtf((float)degw + 1.0f);
    float4 part = agg_partial(hb, w, p, lane, dd, degw);
    if (p == 1) *(float4*)&sh[nl][lane * 4] = part;
    __syncthreads();
    if (p == 0) {
        float4 o = *(float4*)&sh[nl][lane * 4];
        int c = lane * 4;
        float4 h;
        h.x = fmaxf(part.x + o.x + __ldg(bias + c + 0), 0.f);
        h.y = fmaxf(part.y + o.y + __ldg(bias + c + 1), 0.f);
        h.z = fmaxf(part.z + o.z + __ldg(bias + c + 2), 0.f);
        h.w = fmaxf(part.w + o.w + __ldg(bias + c + 3), 0.f);
        // per-node head: y[j] = h-row · Wl[:,j], warp-reduced
        float y[CC];
#pragma unroll
        for (int j = 0; j < CC; j++)
            y[j] = h.x * __ldg(Wl + (c + 0) * CC + j)
                 + h.y * __ldg(Wl + (c + 1) * CC + j)
                 + h.z * __ldg(Wl + (c + 2) * CC + j)
                 + h.w * __ldg(Wl + (c + 3) * CC + j);
#pragma unroll
        for (int off = 16; off; off >>= 1)
#pragma unroll
            for (int j = 0; j < CC; j++)
                y[j] += __shfl_xor_sync(0xffffffffu, y[j], off);
        if (lane == 0) {
            int b = g_b64 ? (int)((const long long*)bat)[w] : ((const int*)bat)[w];
            float inv = g_invcnt[b];
#pragma unroll
            for (int j = 0; j < CC; j++)
                atomicAdd(out + b * CC + j, y[j] * inv);
        }
    }
}

// ---------------------------------------------------------------------------
// tf32 HMMA GEMM: out_bf16[128-row tile][128] = X @ W, K=128. Dense fp32 in.
// ---------------------------------------------------------------------------
__device__ __forceinline__ float to_tf32(float f) {
    uint32_t o;
    asm("cvt.rna.tf32.f32 %0, %1;" : "=r"(o) : "f"(f));
    return __uint_as_float(o);
}

__global__ void __launch_bounds__(256, 1)
gemm_mma(const float* __restrict__ X, const float* __restrict__ W,
         uint32_t* __restrict__ outb) {
    extern __shared__ float sm[];
    float* Xs = sm;              // 128 x TS
    float* Ws = sm + 128 * TS;   // 128 x TS
    int tid = threadIdx.x;
    int r0 = blockIdx.x * 128;

#pragma unroll
    for (int j = 0; j < 16; j++) {
        int f = tid + j * 256;
        int row = f >> 5, c4 = f & 31;
        int gr = r0 + row;
        float4 v = make_float4(0.f, 0.f, 0.f, 0.f);
        if (gr < NN) v = __ldg((const float4*)X + gr * 32 + c4);
        v.x = to_tf32(v.x); v.y = to_tf32(v.y);
        v.z = to_tf32(v.z); v.w = to_tf32(v.w);
        *(float4*)(Xs + row * TS + c4 * 4) = v;
        float4 w = ((const float4*)W)[row * 32 + c4];
        w.x = to_tf32(w.x); w.y = to_tf32(w.y);
        w.z = to_tf32(w.z); w.w = to_tf32(w.w);
        *(float4*)(Ws + row * TS + c4 * 4) = w;
    }
    __syncthreads();

    int lane = tid & 31, wid = tid >> 5;
    int mw = (wid >> 1) * 32;
    int nw = (wid & 1) * 64;
    int gq = lane >> 2;
    int tq = lane & 3;

    float acc[2][8][4];
#pragma unroll
    for (int m = 0; m < 2; m++)
#pragma unroll
        for (int n = 0; n < 8; n++)
#pragma unroll
            for (int q = 0; q < 4; q++) acc[m][n][q] = 0.f;

#pragma unroll
    for (int kt = 0; kt < 16; kt++) {
        int k0 = kt * 8;
        uint32_t b0[8], b1[8];
        const float* wrow0 = Ws + (k0 + tq) * TS + nw + gq;
        const float* wrow1 = wrow0 + 4 * TS;
#pragma unroll
        for (int n = 0; n < 8; n++) {
            b0[n] = __float_as_uint(wrow0[n * 8]);
            b1[n] = __float_as_uint(wrow1[n * 8]);
        }
        uint32_t a[2][4];
#pragma unroll
        for (int m = 0; m < 2; m++) {
            const float* xr = Xs + (mw + m * 16 + gq) * TS + k0 + tq;
            a[m][0] = __float_as_uint(xr[0]);
            a[m][1] = __float_as_uint(xr[8 * TS]);
            a[m][2] = __float_as_uint(xr[4]);
            a[m][3] = __float_as_uint(xr[8 * TS + 4]);
        }
#pragma unroll
        for (int m = 0; m < 2; m++)
#pragma unroll
            for (int n = 0; n < 8; n++)
                asm volatile(
                    "mma.sync.aligned.m16n8k8.row.col.f32.tf32.tf32.f32 "
                    "{%0,%1,%2,%3}, {%4,%5,%6,%7}, {%8,%9}, {%0,%1,%2,%3};"
                    : "+f"(acc[m][n][0]), "+f"(acc[m][n][1]),
                      "+f"(acc[m][n][2]), "+f"(acc[m][n][3])
                    : "r"(a[m][0]), "r"(a[m][1]), "r"(a[m][2]), "r"(a[m][3]),
                      "r"(b0[n]), "r"(b1[n]));
    }

#pragma unroll
    for (int m = 0; m < 2; m++) {
        int r = r0 + mw + m * 16 + gq;
#pragma unroll
        for (int n = 0; n < 8; n++) {
            int cp = (nw >> 1) + n * 4 + tq;     // bf16x2 column index
            if (r < NN)
                outb[r * 64 + cp] = pack_bf16(acc[m][n][0], acc[m][n][1]);
            if (r + 8 < NN)
                outb[(r + 8) * 64 + cp] = pack_bf16(acc[m][n][2], acc[m][n][3]);
        }
    }
}

extern "C" void kernel_launch(void* const* d_in, const int* in_sizes, int n_in,
                              void* d_out, int out_size) {
    const float* x  = (const float*)d_in[0];
    const void*  ei = d_in[1];
    const void*  bat = d_in[2];
    const float* W1 = (const float*)d_in[3];
    const float* b1 = (const float*)d_in[4];
    const float* W2 = (const float*)d_in[5];
    const float* b2 = (const float*)d_in[6];
    const float* Wl = (const float*)d_in[7];
    const float* bl = (const float*)d_in[8];
    float* out = (float*)d_out;
    int E = in_sizes[1] / 2;

    const int SMEM_GEMM = 2 * 128 * TS * 4;   // 135168 B
    static cudaStream_t s2;
    static cudaEvent_t ev_fork, ev_join;
    static int once = 0;
    if (!once) {
        cudaFuncSetAttribute(gemm_mma, cudaFuncAttributeMaxDynamicSharedMemorySize,
                             SMEM_GEMM);
        cudaStreamCreateWithFlags(&s2, cudaStreamNonBlocking);
        cudaEventCreateWithFlags(&ev_fork, cudaEventDisableTiming);
        cudaEventCreateWithFlags(&ev_join, cudaEventDisableTiming);
        once = 1;
    }

    uint32_t* Hb;
    float* B;
    cudaGetSymbolAddress((void**)&Hb, g_Hbf);
    cudaGetSymbolAddress((void**)&B, g_B);

    int eb = (E + 255) / 256;
    int ab = NN / 4;                  // 12500 blocks, 4 nodes each (exact)
    int nb = (NN + 255) / 256;
    int gb = (NN + 127) / 128;

    // fork: GEMM1 + prep (inputs only) parallel to detect+fill
    cudaEventRecord(ev_fork, 0);
    cudaStreamWaitEvent(s2, ev_fork, 0);
    gemm_mma<<<gb, 256, SMEM_GEMM, s2>>>(x, W1, Hb);
    prep_kernel<<<1, GG, 0, s2>>>(bat, bl, out);
    cudaEventRecord(ev_join, s2);

    detect_kernel<<<1, 32>>>((const unsigned*)ei, (const unsigned*)bat);
    fill_direct_kernel<<<eb, 256>>>(ei, E);

    cudaStreamWaitEvent(0, ev_join, 0);       // join before agg1
    agg_kernel<<<ab, 256>>>(Hb, b1, B);
    gemm_mma<<<gb, 256, SMEM_GEMM>>>(B, W2, Hb);
    agg_pool_head_kernel<<<ab, 256>>>(Hb, b2, bat, Wl, out);
    cleanup_deg_kernel<<<nb, 256>>>();        // restore deg=0 for next replay
}

// round 17
// speedup vs baseline: 1.1298x; 1.1298x over previous
#include <cuda_runtime.h>
#include <cstdint>

#define NN 50000
#define HH 128
#define GG 512
#define CC 10
#define CAP 64        // padded CSR row capacity (Poisson(16): P(deg>=64) ~ 1e-20)
#define TS 132        // padded SMEM row stride (floats)

// ---------------- scratch (no allocs allowed) ----------------
__device__ __align__(16) uint32_t g_Hbf[NN * 64];    // gemm out, bf16x2 (gather target)
__device__ __align__(16) float g_B[NN * HH];         // fp32 intermediate
__device__ float g_invcnt[GG];
__device__ int   g_deg[NN];
__device__ __align__(16) int g_csr[NN * CAP];        // padded CSR rows
__device__ int g_ei64;
__device__ int g_b64;

__device__ __forceinline__ float blo(uint32_t v) { return __uint_as_float(v << 16); }
__device__ __forceinline__ float bhi(uint32_t v) { return __uint_as_float(v & 0xffff0000u); }
__device__ __forceinline__ uint32_t pack_bf16(float lo, float hi) {
    uint32_t r;
    asm("cvt.rn.bf16x2.f32 %0, %1, %2;" : "=r"(r) : "f"(hi), "f"(lo));
    return r;
}

// ---------------- critical-path init: deg zero + dtype detect ----------------
__global__ void init_deg_kernel(const unsigned* __restrict__ ei,
                                const unsigned* __restrict__ bat) {
    int i = blockIdx.x * blockDim.x + threadIdx.x;
    if (i < NN) g_deg[i] = 0;
    if (blockIdx.x == 0 && threadIdx.x < 32) {
        unsigned oe = 0, ob = 0;
        int lane = threadIdx.x;
        for (int j = lane; j < 1024; j += 32) {
            oe |= ei[2 * j + 1];
            ob |= bat[2 * j + 1];
        }
#pragma unroll
        for (int off = 16; off; off >>= 1) {
            oe |= __shfl_xor_sync(0xffffffffu, oe, off);
            ob |= __shfl_xor_sync(0xffffffffu, ob, off);
        }
        if (lane == 0) { g_ei64 = (oe == 0u); g_b64 = (ob == 0u); }
    }
}

// ---------------- side-stream prep: inv counts via binary search + out=bl ------
__global__ void prep_kernel(const void* __restrict__ bat,
                            const float* __restrict__ bl,
                            float* __restrict__ out) {
    __shared__ int sb64;
    int t = threadIdx.x;                       // 512 threads
    if (t < 32) {
        unsigned ob = 0;
        for (int j = t; j < 1024; j += 32) ob |= ((const unsigned*)bat)[2 * j + 1];
#pragma unroll
        for (int off = 16; off; off >>= 1) ob |= __shfl_xor_sync(0xffffffffu, ob, off);
        if (t == 0) sb64 = (ob == 0u);
    }
    __syncthreads();
    int b64 = sb64;
    int lo = 0, hi = NN;
    while (lo < hi) {
        int mid = (lo + hi) >> 1;
        long long v = b64 ? ((const long long*)bat)[mid] : (long long)((const int*)bat)[mid];
        if (v < (long long)t) lo = mid + 1; else hi = mid;
    }
    int l1 = lo;
    lo = 0; hi = NN;
    while (lo < hi) {
        int mid = (lo + hi) >> 1;
        long long v = b64 ? ((const long long*)bat)[mid] : (long long)((const int*)bat)[mid];
        if (v < (long long)(t + 1)) lo = mid + 1; else hi = mid;
    }
    int cnt = lo - l1;
    g_invcnt[t] = 1.0f / fmaxf((float)cnt, 1.0f);
#pragma unroll
    for (int j = 0; j < CC; j++) out[t * CC + j] = __ldg(bl + j);
}

// ---------------- single-pass padded-CSR fill (deg counted in place) ----------
__global__ void fill_direct_kernel(const void* __restrict__ ei, int E) {
    int e = blockIdx.x * blockDim.x + threadIdx.x;
    if (e >= E) return;
    int src, dst;
    if (g_ei64) {
        src = (int)((const long long*)ei)[e];
        dst = (int)((const long long*)ei)[E + e];
    } else {
        src = ((const int*)ei)[e];
        dst = ((const int*)ei)[E + e];
    }
    int slot = atomicAdd(&g_deg[dst], 1);
    g_csr[dst * CAP + slot] = src;
}

// ---------------- CSR aggregation core (bf16 gather, fp32 accumulate) ----------
// Exact R13 body: warp-per-node, pair-unrolled, on-the-fly rsqrt.
__device__ __forceinline__ float4 agg_row(const uint32_t* __restrict__ hb,
                                          const float* __restrict__ bias,
                                          int w, int lane) {
    int degw = g_deg[w];
    float dd = rsqrtf((float)degw + 1.0f);
    float sc = dd * dd;
    uint2 sv = __ldg((const uint2*)hb + w * 32 + lane);
    float ax = blo(sv.x) * sc, ay = bhi(sv.x) * sc;
    float az = blo(sv.y) * sc, aw = bhi(sv.y) * sc;
    float bx = 0.f, by = 0.f, bz = 0.f, bw = 0.f;
    const int* row = g_csr + w * CAP;
    int e = 0;
    for (; e + 2 <= degw; e += 2) {
        int sa = row[e], sb = row[e + 1];
        uint2 pa = __ldg((const uint2*)hb + sa * 32 + lane);
        uint2 pb = __ldg((const uint2*)hb + sb * 32 + lane);
        float na = rsqrtf((float)g_deg[sa] + 1.0f) * dd;
        float nb = rsqrtf((float)g_deg[sb] + 1.0f) * dd;
        ax = fmaf(blo(pa.x), na, ax);
        ay = fmaf(bhi(pa.x), na, ay);
        az = fmaf(blo(pa.y), na, az);
        aw = fmaf(bhi(pa.y), na, aw);
        bx = fmaf(blo(pb.x), nb, bx);
        by = fmaf(bhi(pb.x), nb, by);
        bz = fmaf(blo(pb.y), nb, bz);
        bw = fmaf(bhi(pb.y), nb, bw);
    }
    if (e < degw) {
        int sa = row[e];
        uint2 pa = __ldg((const uint2*)hb + sa * 32 + lane);
        float na = rsqrtf((float)g_deg[sa] + 1.0f) * dd;
        ax = fmaf(blo(pa.x), na, ax);
        ay = fmaf(bhi(pa.x), na, ay);
        az = fmaf(blo(pa.y), na, az);
        aw = fmaf(bhi(pa.y), na, aw);
    }
    int c = lane * 4;
    float4 acc;
    acc.x = fmaxf(ax + bx + __ldg(bias + c + 0), 0.f);
    acc.y = fmaxf(ay + by + __ldg(bias + c + 1), 0.f);
    acc.z = fmaxf(az + bz + __ldg(bias + c + 2), 0.f);
    acc.w = fmaxf(aw + bw + __ldg(bias + c + 3), 0.f);
    return acc;
}

// layer-1 agg: fp32 out (gemm2 input)
__global__ void agg_kernel(const uint32_t* __restrict__ hb,
                           const float* __restrict__ bias,
                           float* __restrict__ out) {
    int w = (blockIdx.x * blockDim.x + threadIdx.x) >> 5;
    int lane = threadIdx.x & 31;
    if (w >= NN) return;
    float4 acc = agg_row(hb, bias, w, lane);
    ((float4*)out)[w * 32 + lane] = acc;
}

// layer-2 agg + mean-pool + classifier head fused: REDs 10 floats per node
__global__ void agg_pool_head_kernel(const uint32_t* __restrict__ hb,
                                     const float* __restrict__ bias,
                                     const void* __restrict__ bat,
                                     const float* __restrict__ Wl,
                                     float* __restrict__ out) {
    int w = (blockIdx.x * blockDim.x + threadIdx.x) >> 5;
    int lane = threadIdx.x & 31;
    if (w >= NN) return;
    float4 h = agg_row(hb, bias, w, lane);
    int c = lane * 4;
    float y[CC];
#pragma unroll
    for (int j = 0; j < CC; j++)
        y[j] = h.x * __ldg(Wl + (c + 0) * CC + j)
             + h.y * __ldg(Wl + (c + 1) * CC + j)
             + h.z * __ldg(Wl + (c + 2) * CC + j)
             + h.w * __ldg(Wl + (c + 3) * CC + j);
#pragma unroll
    for (int off = 16; off; off >>= 1)
#pragma unroll
        for (int j = 0; j < CC; j++)
            y[j] += __shfl_xor_sync(0xffffffffu, y[j], off);
    if (lane == 0) {
        int b = g_b64 ? (int)((const long long*)bat)[w] : ((const int*)bat)[w];
        float inv = g_invcnt[b];
#pragma unroll
        for (int j = 0; j < CC; j++)
            asm volatile("red.global.add.f32 [%0], %1;"
                         :: "l"(out + b * CC + j), "f"(y[j] * inv) : "memory");
    }
}

// ---------------------------------------------------------------------------
// tf32 HMMA GEMM: out_bf16[128-row tile][128] = X @ W, K=128. Dense fp32 in.
// ---------------------------------------------------------------------------
__device__ __forceinline__ float to_tf32(float f) {
    uint32_t o;
    asm("cvt.rna.tf32.f32 %0, %1;" : "=r"(o) : "f"(f));
    return __uint_as_float(o);
}

__global__ void __launch_bounds__(256, 1)
gemm_mma(const float* __restrict__ X, const float* __restrict__ W,
         uint32_t* __restrict__ outb) {
    extern __shared__ float sm[];
    float* Xs = sm;              // 128 x TS
    float* Ws = sm + 128 * TS;   // 128 x TS
    int tid = threadIdx.x;
    int r0 = blockIdx.x * 128;

#pragma unroll
    for (int j = 0; j < 16; j++) {
        int f = tid + j * 256;
        int row = f >> 5, c4 = f & 31;
        int gr = r0 + row;
        float4 v = make_float4(0.f, 0.f, 0.f, 0.f);
        if (gr < NN) v = __ldg((const float4*)X + gr * 32 + c4);
        v.x = to_tf32(v.x); v.y = to_tf32(v.y);
        v.z = to_tf32(v.z); v.w = to_tf32(v.w);
        *(float4*)(Xs + row * TS + c4 * 4) = v;
        float4 w = ((const float4*)W)[row * 32 + c4];
        w.x = to_tf32(w.x); w.y = to_tf32(w.y);
        w.z = to_tf32(w.z); w.w = to_tf32(w.w);
        *(float4*)(Ws + row * TS + c4 * 4) = w;
    }
    __syncthreads();

    int lane = tid & 31, wid = tid >> 5;
    int mw = (wid >> 1) * 32;
    int nw = (wid & 1) * 64;
    int gq = lane >> 2;
    int tq = lane & 3;

    float acc[2][8][4];
#pragma unroll
    for (int m = 0; m < 2; m++)
#pragma unroll
        for (int n = 0; n < 8; n++)
#pragma unroll
            for (int q = 0; q < 4; q++) acc[m][n][q] = 0.f;

#pragma unroll
    for (int kt = 0; kt < 16; kt++) {
        int k0 = kt * 8;
        uint32_t b0[8], b1[8];
        const float* wrow0 = Ws + (k0 + tq) * TS + nw + gq;
        const float* wrow1 = wrow0 + 4 * TS;
#pragma unroll
        for (int n = 0; n < 8; n++) {
            b0[n] = __float_as_uint(wrow0[n * 8]);
            b1[n] = __float_as_uint(wrow1[n * 8]);
        }
        uint32_t a[2][4];
#pragma unroll
        for (int m = 0; m < 2; m++) {
            const float* xr = Xs + (mw + m * 16 + gq) * TS + k0 + tq;
            a[m][0] = __float_as_uint(xr[0]);
            a[m][1] = __float_as_uint(xr[8 * TS]);
            a[m][2] = __float_as_uint(xr[4]);
            a[m][3] = __float_as_uint(xr[8 * TS + 4]);
        }
#pragma unroll
        for (int m = 0; m < 2; m++)
#pragma unroll
            for (int n = 0; n < 8; n++)
                asm volatile(
                    "mma.sync.aligned.m16n8k8.row.col.f32.tf32.tf32.f32 "
                    "{%0,%1,%2,%3}, {%4,%5,%6,%7}, {%8,%9}, {%0,%1,%2,%3};"
                    : "+f"(acc[m][n][0]), "+f"(acc[m][n][1]),
                      "+f"(acc[m][n][2]), "+f"(acc[m][n][3])
                    : "r"(a[m][0]), "r"(a[m][1]), "r"(a[m][2]), "r"(a[m][3]),
                      "r"(b0[n]), "r"(b1[n]));
    }

#pragma unroll
    for (int m = 0; m < 2; m++) {
        int r = r0 + mw + m * 16 + gq;
#pragma unroll
        for (int n = 0; n < 8; n++) {
            int cp = (nw >> 1) + n * 4 + tq;     // bf16x2 column index
            if (r < NN)
                outb[r * 64 + cp] = pack_bf16(acc[m][n][0], acc[m][n][1]);
            if (r + 8 < NN)
                outb[(r + 8) * 64 + cp] = pack_bf16(acc[m][n][2], acc[m][n][3]);
        }
    }
}

extern "C" void kernel_launch(void* const* d_in, const int* in_sizes, int n_in,
                              void* d_out, int out_size) {
    const float* x  = (const float*)d_in[0];
    const void*  ei = d_in[1];
    const void*  bat = d_in[2];
    const float* W1 = (const float*)d_in[3];
    const float* b1 = (const float*)d_in[4];
    const float* W2 = (const float*)d_in[5];
    const float* b2 = (const float*)d_in[6];
    const float* Wl = (const float*)d_in[7];
    const float* bl = (const float*)d_in[8];
    float* out = (float*)d_out;
    int E = in_sizes[1] / 2;

    const int SMEM_GEMM = 2 * 128 * TS * 4;   // 135168 B
    static cudaStream_t s2;
    static cudaEvent_t ev_fork, ev_join;
    static int once = 0;
    if (!once) {
        cudaFuncSetAttribute(gemm_mma, cudaFuncAttributeMaxDynamicSharedMemorySize,
                             SMEM_GEMM);
        cudaStreamCreateWithFlags(&s2, cudaStreamNonBlocking);
        cudaEventCreateWithFlags(&ev_fork, cudaEventDisableTiming);
        cudaEventCreateWithFlags(&ev_join, cudaEventDisableTiming);
        once = 1;
    }

    uint32_t* Hb;
    float* B;
    cudaGetSymbolAddress((void**)&Hb, g_Hbf);
    cudaGetSymbolAddress((void**)&B, g_B);

    int eb = (E + 255) / 256;
    int nb32 = (NN * 32 + 255) / 256;
    int nb = (NN + 255) / 256;
    int gb = (NN + 127) / 128;

    // fork: GEMM1 + prep (inputs only) parallel to the CSR-build chain
    cudaEventRecord(ev_fork, 0);
    cudaStreamWaitEvent(s2, ev_fork, 0);
    gemm_mma<<<gb, 256, SMEM_GEMM, s2>>>(x, W1, Hb);
    prep_kernel<<<1, GG, 0, s2>>>(bat, bl, out);
    cudaEventRecord(ev_join, s2);

    init_deg_kernel<<<nb, 256>>>((const unsigned*)ei, (const unsigned*)bat);
    fill_direct_kernel<<<eb, 256>>>(ei, E);

    cudaStreamWaitEvent(0, ev_join, 0);       // join before agg1
    agg_kernel<<<nb32, 256>>>(Hb, b1, B);
    gemm_mma<<<gb, 256, SMEM_GEMM>>>(B, W2, Hb);
    agg_pool_head_kernel<<<nb32, 256>>>(Hb, b2, bat, Wl, out);
}